// round 4
// baseline (speedup 1.0000x reference)
#include <cuda_runtime.h>
#include <cuda_bf16.h>

// out[b,o] = sum over UNIQUE keys k=i0*350+i1 in batch row b of W[k,o], + bias[o]
// (reference scatters 1.0 with .set, so duplicate hits count once)

#define B      32
#define NHITS  200
#define D1     350
#define OUTN   5
#define NT     224          // 7 warps, covers 200 hits exactly
#define NW     (NT / 32)
#define HSZ    512          // hash table slots (power of two)
#define HMASK  (HSZ - 1)
#define EMPTY  (-1)

__global__ __launch_bounds__(NT, 1)
void prtnn_kernel(const int* __restrict__ x,
                  const float* __restrict__ W,
                  const float* __restrict__ bias,
                  float* __restrict__ out)
{
    __shared__ int   tab[HSZ];
    __shared__ float wacc[NW][OUTN];

    const int b   = blockIdx.x;
    const int t   = threadIdx.x;
    const int wid = t >> 5;
    const int lid = t & 31;

    // Kick off the scattered x loads immediately (longest-latency leaf).
    // All offsets fit in 32-bit: b*200*3 + t*3 < 19200.
    int k = 0;
    if (t < NHITS) {
        const int* hit = x + (b * NHITS + t) * 3;
        k = hit[1] * D1 + hit[2];          // 0 .. 2150399
    }

    // Init hash table in parallel with the x loads (independent work).
    #pragma unroll
    for (int i = t; i < HSZ; i += NT) tab[i] = EMPTY;
    __syncthreads();

    // Speculatively gather the W row NOW — independent of the dedup result,
    // so the CAS/probe latency hides under this DRAM round. k*5 <= 10.75M,
    // 32-bit math throughout.
    float w0 = 0.f, w1 = 0.f, w2 = 0.f, w3 = 0.f, w4 = 0.f;
    if (t < NHITS) {
        const float* w = W + k * OUTN;
        w0 = __ldg(w + 0);
        w1 = __ldg(w + 1);
        w2 = __ldg(w + 2);
        w3 = __ldg(w + 3);
        w4 = __ldg(w + 4);
    }

    // O(1) dedup: exactly one thread per distinct key wins the CAS.
    // Which thread wins is schedule-dependent, but the SET of unique keys
    // (and thus the masked sum) is not.
    bool unique = false;
    if (t < NHITS) {
        unsigned h = (((unsigned)k * 2654435761u) >> 20) & HMASK;
        while (true) {
            int old = atomicCAS(&tab[h], EMPTY, k);
            if (old == EMPTY) { unique = true; break; }   // inserted: winner
            if (old == k)     { break; }                  // duplicate
            h = (h + 1) & HMASK;                          // linear probe
        }
    }

    const float m = unique ? 1.0f : 0.0f;
    float c[OUTN] = { m * w0, m * w1, m * w2, m * w3, m * w4 };

    // Per-warp fixed-pairing shuffle reduction (deterministic).
    #pragma unroll
    for (int o = 0; o < OUTN; ++o) {
        float v = c[o];
        #pragma unroll
        for (int s = 16; s > 0; s >>= 1)
            v += __shfl_down_sync(0xFFFFFFFFu, v, s);
        if (lid == 0) wacc[wid][o] = v;
    }
    __syncthreads();

    // Final 7-way sum, fixed order, by 5 threads.
    if (t < OUTN) {
        float v = bias[t];
        #pragma unroll
        for (int w = 0; w < NW; ++w) v += wacc[w][t];
        out[b * OUTN + t] = v;
    }
}

extern "C" void kernel_launch(void* const* d_in, const int* in_sizes, int n_in,
                              void* d_out, int out_size)
{
    const int*   x    = (const int*)d_in[0];    // [32, 200, 3] int32
    const float* W    = (const float*)d_in[1];  // [2150400, 5] f32
    const float* bias = (const float*)d_in[2];  // [5] f32
    float*       out  = (float*)d_out;          // [32, 5] f32

    prtnn_kernel<<<B, NT>>>(x, W, bias, out);
}

// round 6
// speedup vs baseline: 1.0489x; 1.0489x over previous
#include <cuda_runtime.h>
#include <cuda_bf16.h>

// out[b,o] = sum over UNIQUE keys k=i0*350+i1 in batch row b of W[k,o], + bias[o]
// (reference scatters 1.0 with .set, so duplicate hits count once)

#define B      32
#define NHITS  200
#define D1     350
#define OUTN   5
#define NT     224          // 7 warps, covers 200 hits exactly
#define NW     (NT / 32)
#define HSZ    512          // hash table slots (power of two)
#define HMASK  (HSZ - 1)
#define EMPTY  (-1)

__global__ __launch_bounds__(NT, 1)
void prtnn_kernel(const int* __restrict__ x,
                  const float* __restrict__ W,
                  const float* __restrict__ bias,
                  float* __restrict__ out)
{
    __shared__ int   tab[HSZ];
    __shared__ float wacc[NW][OUTN];

    const int b   = blockIdx.x;
    const int t   = threadIdx.x;
    const int wid = t >> 5;
    const int lid = t & 31;

    // Kick off the scattered x loads immediately (longest-latency leaf).
    int k = 0;
    if (t < NHITS) {
        const int* hit = x + (b * NHITS + t) * 3;
        k = __ldg(hit + 1) * D1 + __ldg(hit + 2);   // 0 .. 2150399
    }

    // Init hash table in parallel with the x loads (independent work).
    #pragma unroll
    for (int i = t; i < HSZ; i += NT) tab[i] = EMPTY;
    __syncthreads();

    // Speculative W-row gather as TWO 16B loads instead of five 4B loads.
    // The 5-float row [k*5, k*5+5) always lies inside the 8-float window
    // starting at base = (k*5) & ~3 (16B-aligned; max index 10,751,999 = last
    // element of W, in bounds). Select the needed 5 by r = (k*5) & 3.
    float a0=0.f,a1=0.f,a2=0.f,a3=0.f,a4=0.f,a5=0.f,a6=0.f,a7=0.f;
    int r = 0;
    if (t < NHITS) {
        const int e  = k * OUTN;          // <= 10,751,995 : fits in int
        const int base = e & ~3;
        r = e & 3;
        const float4 p = __ldg((const float4*)(W + base));
        const float4 q = __ldg((const float4*)(W + base + 4));
        a0=p.x; a1=p.y; a2=p.z; a3=p.w; a4=q.x; a5=q.y; a6=q.z; a7=q.w;
    }

    // O(1) dedup runs while the two LDG.128 are in flight. Exactly one thread
    // per distinct key wins the CAS; which one is schedule-dependent, but the
    // SET of unique keys (and thus the masked sum) is not.
    bool unique = false;
    if (t < NHITS) {
        unsigned h = (((unsigned)k * 2654435761u) >> 20) & HMASK;
        while (true) {
            int old = atomicCAS(&tab[h], EMPTY, k);
            if (old == EMPTY) { unique = true; break; }   // inserted: winner
            if (old == k)     { break; }                  // duplicate
            h = (h + 1) & HMASK;                          // linear probe
        }
    }

    // Lane-select the 5 row values (predicated SELs, no indexed array).
    float w0 = (r==0) ? a0 : (r==1) ? a1 : (r==2) ? a2 : a3;
    float w1 = (r==0) ? a1 : (r==1) ? a2 : (r==2) ? a3 : a4;
    float w2 = (r==0) ? a2 : (r==1) ? a3 : (r==2) ? a4 : a5;
    float w3 = (r==0) ? a3 : (r==1) ? a4 : (r==2) ? a5 : a6;
    float w4 = (r==0) ? a4 : (r==1) ? a5 : (r==2) ? a6 : a7;

    const float m = unique ? 1.0f : 0.0f;
    float c[OUTN] = { m * w0, m * w1, m * w2, m * w3, m * w4 };

    // Per-warp fixed-pairing shuffle reduction (deterministic).
    #pragma unroll
    for (int o = 0; o < OUTN; ++o) {
        float v = c[o];
        #pragma unroll
        for (int s = 16; s > 0; s >>= 1)
            v += __shfl_down_sync(0xFFFFFFFFu, v, s);
        if (lid == 0) wacc[wid][o] = v;
    }
    __syncthreads();

    // Final 7-way sum, fixed order, by 5 threads.
    if (t < OUTN) {
        float v = bias[t];
        #pragma unroll
        for (int w = 0; w < NW; ++w) v += wacc[w][t];
        out[b * OUTN + t] = v;
    }
}

extern "C" void kernel_launch(void* const* d_in, const int* in_sizes, int n_in,
                              void* d_out, int out_size)
{
    const int*   x    = (const int*)d_in[0];    // [32, 200, 3] int32
    const float* W    = (const float*)d_in[1];  // [2150400, 5] f32
    const float* bias = (const float*)d_in[2];  // [5] f32
    float*       out  = (float*)d_out;          // [32, 5] f32

    prtnn_kernel<<<B, NT>>>(x, W, bias, out);
}